// round 12
// baseline (speedup 1.0000x reference)
#include <cuda_runtime.h>
#include <math.h>

#define H 128
#define W 128
#define TILE 32
#define MAXN 16384
#define NB 8192
#define CAP 16
#define GRID 296
#define BLOCK 1024
#define TERM_T 1.0e-8f
#define SKIP_L2 -23.25f   // log2(1e-7); below this alpha < 1e-7
#define BATCH 64
#define NSEG 16
#define NLIST 256         // 16 tiles x 16 two-row slabs
#define CAPQ 2048

__device__ __forceinline__ float ex2f(float x) {
    float y; asm("ex2.approx.ftz.f32 %0, %1;" : "=f"(y) : "f"(x)); return y;
}

// ---------------- scratch (device globals; zero-initialized at load) --------
__device__ unsigned long long g_key [MAXN];
__device__ int                g_bucket[MAXN];
__device__ int                g_bucketCnt[NB];     // re-zeroed each run
__device__ unsigned long long g_bkey[NB * CAP];

__device__ float4 g_u1[MAXN];   // mx, A', B', C'   (conic * -0.5*log2 e)
__device__ float4 g_uT[MAXN];   // my, E', log2(op), -
__device__ float4 g_u3[MAXN];   // colR, colG, colB, depth
__device__ float4 g_u4[MAXN];   // bbox
__device__ float2 g_u5[MAXN];   // y-significance interval (ylo, yhi)

__device__ float4 g_s1[MAXN];   // depth-sorted
__device__ float4 g_sT[MAXN];
__device__ float4 g_s3[MAXN];
__device__ float4 g_s4[MAXN];
__device__ float2 g_s5[MAXN];

__device__ float4 g_q1[NLIST][CAPQ];
__device__ float4 g_qT[NLIST][CAPQ];
__device__ float4 g_q3[NLIST][CAPQ];

// ---------------- grid barrier (monotone generations, replay-safe) ----------
__device__ unsigned g_arrive = 0;
__device__ volatile unsigned g_release = 0;

__device__ __forceinline__ void grid_barrier()
{
    __syncthreads();
    if (threadIdx.x == 0) {
        __threadfence();
        unsigned old = atomicAdd(&g_arrive, 1u);
        unsigned target = old / GRID + 1u;
        if ((old % GRID) == GRID - 1u) {
            atomicAdd((unsigned*)&g_release, 1u);
        } else {
            while (g_release < target) { }
        }
        __threadfence();
    }
    __syncthreads();
}

// ---------------- tile mask ----------------
__device__ __forceinline__ bool tile_mask(float4 r, int tile)
{
    float wlo = (float)((tile & 3) * TILE);
    float hlo = (float)((tile >> 2) * TILE);
    float tlx = fmaxf(r.x, wlo);
    float tly = fmaxf(r.y, hlo);
    float brx = fminf(r.z, wlo + (float)(TILE - 1));
    float bry = fminf(r.w, hlo + (float)(TILE - 1));
    return (brx > tlx) && (bry > tly);
}

__device__ __forceinline__ int wscan_incl(int v, int lane)
{
    #pragma unroll
    for (int d = 1; d < 32; d <<= 1) {
        int u = __shfl_up_sync(0xffffffffu, v, d);
        if (lane >= d) v += u;
    }
    return v;
}

// ---------------- the whole pipeline in ONE kernel ----------------
__global__ void __launch_bounds__(BLOCK, 2) mega_kernel(
    const float* __restrict__ means,
    const float* __restrict__ cov,
    const float* __restrict__ color,
    const float* __restrict__ opacity,
    const float* __restrict__ depths,
    int n, float* __restrict__ out)
{
    const int tid  = threadIdx.x;
    const int b    = blockIdx.x;
    const int lane = tid & 31;
    const int warp = tid >> 5;
    const int gt   = b * BLOCK + tid;
    const int nch  = (n + 255) >> 8;

    // aliased smem arena (uses are time-separated)
    __shared__ __align__(16) char smem_raw[49152];   // 48 KB
    int*      sOff   = (int*)smem_raw;                         // B: 32 KB
    int*      swsum  = (int*)(smem_raw + 32768);               // B: 128 B
    unsigned* sball  = (unsigned*)smem_raw;                    // C: 2 KB
    int*      schcnt = (int*)(smem_raw + 2048);                // C
    int*      schoff = (int*)(smem_raw + 2560);                // C
    float4*   sb1    = (float4*)smem_raw;                      // D: 16 KB
    float4*   sbT    = (float4*)(smem_raw + 16384);            // D: 16 KB
    float4*   sb3    = (float4*)(smem_raw + 32768);            // D: 16 KB
    float*    pres   = (float*)smem_raw;                       // D fold: 20 KB

    // ================= Phase A: preprocess + bucket place =================
    if (gt < n) {
        int i = gt;
        float2 mv  = ((const float2*)means)[i];
        float4 cv  = ((const float4*)cov)[i];
        float mx  = mv.x, my = mv.y;
        float c00 = cv.x, c01 = cv.y, c10 = cv.z, c11 = cv.w;

        // match JAX sequencing for the mask-critical radii math
        float det = __fsub_rn(__fmul_rn(c00, c11), __fmul_rn(c01, c10));
        float mid = __fmul_rn(0.5f, __fadd_rn(c00, c11));
        float s   = sqrtf(fmaxf(__fsub_rn(__fmul_rn(mid, mid), det), 0.1f));
        float lam = fmaxf(__fadd_rn(mid, s), __fsub_rn(mid, s));
        float radii = __fmul_rn(3.0f, ceilf(sqrtf(lam)));

        float rminx = fminf(fmaxf(__fsub_rn(mx, radii), 0.0f), (float)(W-1));
        float rminy = fminf(fmaxf(__fsub_rn(my, radii), 0.0f), (float)(H-1));
        float rmaxx = fminf(fmaxf(__fadd_rn(mx, radii), 0.0f), (float)(W-1));
        float rmaxy = fminf(fmaxf(__fadd_rn(my, radii), 0.0f), (float)(H-1));

        float inv = __fdiv_rn(1.0f, det);
        const float L = -0.72134752044448170368f;  // -0.5*log2(e)
        float ca = __fmul_rn(c11, inv) * L;                                   // A' < 0
        float cc = __fmul_rn(c00, inv) * L;                                   // C' < 0
        float cb = __fadd_rn(__fmul_rn(-c01, inv), __fmul_rn(-c10, inv)) * L; // B'

        float dep = depths[i];
        float ol2 = log2f(opacity[i]);

        // exact dx-maximized bound: pw <= E'*dy^2 + ol2
        float E  = cc - (cb * cb) / (4.0f * ca);          // <= C' < 0
        float Rr = sqrtf(fmaxf(0.0f, (SKIP_L2 - 1.0f - ol2) / E));

        unsigned int db = __float_as_uint(dep);
        unsigned long long key = ((unsigned long long)db << 32) | (unsigned int)i;
        g_key[i] = key;

        int bk = (int)((dep - 0.19f) * 800.0f);
        bk = max(0, min(NB - 1, bk));
        g_bucket[i] = bk;
        int slot = atomicAdd(&g_bucketCnt[bk], 1);
        if (slot < CAP) g_bkey[bk * CAP + slot] = key;

        g_u1[i] = make_float4(mx, ca, cb, cc);
        g_uT[i] = make_float4(my, E, ol2, 0.0f);
        g_u3[i] = make_float4(color[3*i+0], color[3*i+1], color[3*i+2], dep);
        g_u4[i] = make_float4(rminx, rminy, rmaxx, rmaxy);
        g_u5[i] = make_float2(my - Rr, my + Rr);
    }
    grid_barrier();

    // ===== Phase B: redundant per-block bucket scan + rank + scatter =====
    {
        int base = tid * (NB / BLOCK);     // 8 buckets per thread
        int c[NB / BLOCK];
        int s = 0;
        #pragma unroll
        for (int k = 0; k < NB / BLOCK; ++k) { c[k] = g_bucketCnt[base + k]; s += c[k]; }
        int incl = wscan_incl(s, lane);
        if (lane == 31) swsum[warp] = incl;
        __syncthreads();
        if (warp == 0) {
            int v = swsum[lane];
            int iv = wscan_incl(v, lane);
            swsum[lane] = iv - v;
        }
        __syncthreads();
        int e = swsum[warp] + incl - s;
        #pragma unroll
        for (int k = 0; k < NB / BLOCK; ++k) { sOff[base + k] = e; e += c[k]; }
        __syncthreads();

        if (gt < n) {
            int i = gt;
            int bk = g_bucket[i];
            unsigned long long ki = g_key[i];
            int cnt = min(g_bucketCnt[bk], CAP);
            int kb = bk * CAP;
            int r = sOff[bk];
            for (int j = 0; j < cnt; ++j)
                r += (g_bkey[kb + j] < ki);
            g_s1[r] = g_u1[i];
            g_sT[r] = g_uT[i];
            g_s3[r] = g_u3[i];
            g_s4[r] = g_u4[i];
            g_s5[r] = g_u5[i];
        }
    }
    grid_barrier();

    // ---- blocks 256..295: zero bucket counters for next replay, exit ----
    if (b >= NLIST) {
        int idx = (b - NLIST) * BLOCK + tid;
        if (idx < NB) g_bucketCnt[idx] = 0;
        return;
    }

    // ===== Phase C: build list for (tile, slab) = (b>>4, b&15) =====
    const int tile = b >> 4;
    const int slab = b & 15;                    // 2-row slab
    const float sy0 = (float)((tile >> 2) * TILE + slab * 2);
    const float sy1 = sy0 + 1.0f;
    int listCnt;
    {
        // count + ballot cache; warp w handles chunks w and w+32
        for (int chunk = warp; chunk < nch; chunk += 32) {
            int cnt = 0;
            #pragma unroll
            for (int s = 0; s < 8; ++s) {
                int i = chunk * 256 + s * 32 + lane;
                bool m = false;
                if (i < n && tile_mask(g_s4[i], tile)) {
                    float2 yy = g_s5[i];
                    m = (yy.y >= sy0) && (yy.x <= sy1);
                }
                unsigned ball = __ballot_sync(0xffffffffu, m);
                if (lane == 0) sball[chunk * 8 + s] = ball;
                cnt += __popc(ball);
            }
            if (lane == 0) schcnt[chunk] = cnt;
        }
        __syncthreads();
        if (warp == 0) {
            int a  = (lane < nch) ? schcnt[lane] : 0;
            int b2 = (32 + lane < nch) ? schcnt[32 + lane] : 0;
            int sA = wscan_incl(a, lane);
            int tA = __shfl_sync(0xffffffffu, sA, 31);
            int sB = wscan_incl(b2, lane);
            int tB = __shfl_sync(0xffffffffu, sB, 31);
            if (lane < nch)      schoff[lane]      = sA - a;
            if (32 + lane < nch) schoff[32 + lane] = tA + sB - b2;
            if (lane == 0)       schoff[63]        = tA + tB;   // total
        }
        __syncthreads();
        listCnt = min(schoff[63], CAPQ);
        for (int chunk = warp; chunk < nch; chunk += 32) {
            int off = schoff[chunk];
            #pragma unroll
            for (int s = 0; s < 8; ++s) {
                unsigned ball = sball[chunk * 8 + s];
                if (ball & (1u << lane)) {
                    int i = chunk * 256 + s * 32 + lane;
                    int pos = off + __popc(ball & ((1u << lane) - 1u));
                    if (pos < CAPQ) {
                        g_q1[b][pos] = g_s1[i];
                        g_qT[b][pos] = g_sT[i];
                        g_q3[b][pos] = g_s3[i];
                    }
                }
                off += __popc(ball);
            }
        }
    }
    __syncthreads();

    // ===== Phase D: render 64 px x 16 depth segments =====
    {
        int seg = tid >> 6;                // 0..15 front-to-back segments
        int l   = tid & 63;                // pixel within 32x2 slab
        int px = (tile & 3) * TILE + (l & 31);
        int py = (tile >> 2) * TILE + slab * 2 + (l >> 5);
        float fx = (float)px;
        float fy = (float)py;

        int cnt = listCnt;
        int q   = (cnt + NSEG - 1) >> 4;
        int sbeg = seg * q;
        int send = min(cnt, sbeg + q);

        float T = 1.0f;
        float cr = 0.0f, cg = 0.0f, cbl = 0.0f, cd = 0.0f;

        for (int base = 0; base < q; base += BATCH) {
            {
                int mload = send - (sbeg + base);
                int gidx  = sbeg + base + l;
                if (l < mload && l < BATCH) {
                    sb1[seg * BATCH + l] = g_q1[b][gidx];
                    sbT[seg * BATCH + l] = g_qT[b][gidx];
                    sb3[seg * BATCH + l] = g_q3[b][gidx];
                } else if (l < BATCH) {
                    sbT[seg * BATCH + l] = make_float4(0.f, 0.f, -1.0e9f, 0.f);
                }
            }
            __syncthreads();

            int m = min(BATCH, send - (sbeg + base));
            if (m > 0 && T >= TERM_T) {
                for (int k = 0; k < m; ++k) {
                    float4 pt = sbT[seg * BATCH + k];     // my, E', ol2
                    float dy = fy - pt.x;
                    float rt = fmaf(pt.y * dy, dy, pt.z); // warp-uniform row bound
                    if (rt > SKIP_L2) {
                        float4 p1 = sb1[seg * BATCH + k]; // mx, A', B', C'
                        float dx = fx - p1.x;
                        float u  = p1.z * dy;
                        float v  = fmaf(p1.w * dy, dy, pt.z);
                        float pw = fmaf(fmaf(p1.y, dx, u), dx, v);
                        if (pw > SKIP_L2) {
                            float alpha = fminf(ex2f(pw), 0.99f);
                            float wgt = T * alpha;
                            float4 p3 = sb3[seg * BATCH + k];
                            cr  = fmaf(wgt, p3.x, cr);
                            cg  = fmaf(wgt, p3.y, cg);
                            cbl = fmaf(wgt, p3.z, cbl);
                            cd  = fmaf(wgt, p3.w, cd);
                            T  -= wgt;
                        }
                    }
                    if ((k & 31) == 31 &&
                        __all_sync(0xffffffffu, T < TERM_T)) break;
                }
            }
            if (__syncthreads_and(T < TERM_T)) break;
        }

        // fold 16 depth segments front-to-back: c = cF + TF*cB, T = TF*TB
        __syncthreads();                   // batches dead; alias fold buffer
        pres[0 * BLOCK + tid] = cr;  pres[1 * BLOCK + tid] = cg;
        pres[2 * BLOCK + tid] = cbl; pres[3 * BLOCK + tid] = cd;
        pres[4 * BLOCK + tid] = T;
        __syncthreads();
        if (tid < 64) {
            float crO = pres[0 * BLOCK + tid + 15 * 64];
            float cgO = pres[1 * BLOCK + tid + 15 * 64];
            float cbO = pres[2 * BLOCK + tid + 15 * 64];
            float cdO = pres[3 * BLOCK + tid + 15 * 64];
            float TO  = pres[4 * BLOCK + tid + 15 * 64];
            #pragma unroll
            for (int s = 14; s >= 0; --s) {
                int o = tid + s * 64;
                float Tf = pres[4 * BLOCK + o];
                crO = fmaf(Tf, crO, pres[0 * BLOCK + o]);
                cgO = fmaf(Tf, cgO, pres[1 * BLOCK + o]);
                cbO = fmaf(Tf, cbO, pres[2 * BLOCK + o]);
                cdO = fmaf(Tf, cdO, pres[3 * BLOCK + o]);
                TO *= Tf;
            }
            int pix = py * W + px;
            out[pix * 3 + 0]     = crO + TO;
            out[pix * 3 + 1]     = cgO + TO;
            out[pix * 3 + 2]     = cbO + TO;
            out[H * W * 3 + pix] = cdO;
            out[H * W * 4 + pix] = 1.0f - TO;
        }
    }
}

// ---------------- launch ----------------
extern "C" void kernel_launch(void* const* d_in, const int* in_sizes, int n_in,
                              void* d_out, int out_size)
{
    const float* means   = (const float*)d_in[0];
    const float* cov     = (const float*)d_in[1];
    const float* color   = (const float*)d_in[2];
    const float* opacity = (const float*)d_in[3];
    const float* depths  = (const float*)d_in[4];
    int n = in_sizes[4];
    if (n > MAXN) n = MAXN;

    mega_kernel<<<GRID, BLOCK>>>(means, cov, color, opacity, depths, n, (float*)d_out);
}

// round 13
// speedup vs baseline: 1.0457x; 1.0457x over previous
#include <cuda_runtime.h>
#include <math.h>

#define H 128
#define W 128
#define TILE 32
#define MAXN 16384
#define NB 8192
#define CAP 16
#define GRID 296
#define BLOCK 1024
#define TERM_T 1.0e-8f
#define SKIP_L2 -23.25f   // log2(1e-7); below this alpha < 1e-7
#define BATCH 64
#define NSEG 16
#define NLIST 256         // 16 tiles x 16 two-row slabs
#define CAPQ 2048

__device__ __forceinline__ float ex2f(float x) {
    float y; asm("ex2.approx.ftz.f32 %0, %1;" : "=f"(y) : "f"(x)); return y;
}
__device__ __forceinline__ float lg2f(float x) {
    float y; asm("lg2.approx.f32 %0, %1;" : "=f"(y) : "f"(x)); return y;
}

// ---------------- scratch (device globals; zero-initialized at load) --------
__device__ unsigned long long g_key [MAXN];
__device__ int                g_bucket[MAXN];
__device__ int                g_bucketCnt[NB];     // re-zeroed each run
__device__ unsigned long long g_bkey[NB * CAP];

__device__ float4 g_u1[MAXN];   // mx, A', B', C'   (conic * -0.5*log2 e)
__device__ float4 g_uT[MAXN];   // my, E', log2(op), -
__device__ float4 g_u3[MAXN];   // colR, colG, colB, depth
__device__ float4 g_u4[MAXN];   // bbox
__device__ float2 g_u5[MAXN];   // y-significance interval (ylo, yhi)

__device__ float4 g_s1[MAXN];   // depth-sorted
__device__ float4 g_sT[MAXN];
__device__ float4 g_s3[MAXN];
__device__ float4 g_s4[MAXN];
__device__ float2 g_s5[MAXN];

__device__ float4 g_q1[NLIST][CAPQ];
__device__ float4 g_qT[NLIST][CAPQ];
__device__ float4 g_q3[NLIST][CAPQ];

// ---------------- grid barrier (monotone generations, replay-safe) ----------
__device__ unsigned g_arrive = 0;
__device__ volatile unsigned g_release = 0;

__device__ __forceinline__ void grid_barrier()
{
    __syncthreads();
    if (threadIdx.x == 0) {
        __threadfence();
        unsigned old = atomicAdd(&g_arrive, 1u);
        unsigned target = old / GRID + 1u;
        if ((old % GRID) == GRID - 1u) {
            atomicAdd((unsigned*)&g_release, 1u);
        } else {
            while (g_release < target) { }
        }
        __threadfence();
    }
    __syncthreads();
}

// ---------------- tile mask ----------------
__device__ __forceinline__ bool tile_mask(float4 r, int tile)
{
    float wlo = (float)((tile & 3) * TILE);
    float hlo = (float)((tile >> 2) * TILE);
    float tlx = fmaxf(r.x, wlo);
    float tly = fmaxf(r.y, hlo);
    float brx = fminf(r.z, wlo + (float)(TILE - 1));
    float bry = fminf(r.w, hlo + (float)(TILE - 1));
    return (brx > tlx) && (bry > tly);
}

__device__ __forceinline__ int wscan_incl(int v, int lane)
{
    #pragma unroll
    for (int d = 1; d < 32; d <<= 1) {
        int u = __shfl_up_sync(0xffffffffu, v, d);
        if (lane >= d) v += u;
    }
    return v;
}

// ---------------- the whole pipeline in ONE kernel ----------------
__global__ void __launch_bounds__(BLOCK, 2) mega_kernel(
    const float* __restrict__ means,
    const float* __restrict__ cov,
    const float* __restrict__ color,
    const float* __restrict__ opacity,
    const float* __restrict__ depths,
    int n, float* __restrict__ out)
{
    const int tid  = threadIdx.x;
    const int b    = blockIdx.x;
    const int lane = tid & 31;
    const int warp = tid >> 5;
    const int gt   = b * BLOCK + tid;
    const int nch  = (n + 255) >> 8;

    // aliased smem arena (uses are time-separated)
    __shared__ __align__(16) char smem_raw[49152];   // 48 KB
    int*      sOff   = (int*)smem_raw;                         // B: 32 KB
    int*      swsum  = (int*)(smem_raw + 32768);               // B: 128 B
    unsigned* sball  = (unsigned*)smem_raw;                    // C: 2 KB
    int*      schcnt = (int*)(smem_raw + 2048);                // C
    int*      schoff = (int*)(smem_raw + 2560);                // C
    float4*   sb1    = (float4*)smem_raw;                      // D: 16 KB
    float4*   sbT    = (float4*)(smem_raw + 16384);            // D: 16 KB
    float4*   sb3    = (float4*)(smem_raw + 32768);            // D: 16 KB
    float*    pres   = (float*)smem_raw;                       // D fold: 20 KB

    // ================= Phase A: preprocess + bucket place =================
    if (gt < n) {
        int i = gt;
        float2 mv  = ((const float2*)means)[i];
        float4 cv  = ((const float4*)cov)[i];
        float mx  = mv.x, my = mv.y;
        float c00 = cv.x, c01 = cv.y, c10 = cv.z, c11 = cv.w;

        // match JAX sequencing for the mask-critical radii math
        float det = __fsub_rn(__fmul_rn(c00, c11), __fmul_rn(c01, c10));
        float mid = __fmul_rn(0.5f, __fadd_rn(c00, c11));
        float s   = sqrtf(fmaxf(__fsub_rn(__fmul_rn(mid, mid), det), 0.1f));
        float lam = fmaxf(__fadd_rn(mid, s), __fsub_rn(mid, s));
        float radii = __fmul_rn(3.0f, ceilf(sqrtf(lam)));

        float rminx = fminf(fmaxf(__fsub_rn(mx, radii), 0.0f), (float)(W-1));
        float rminy = fminf(fmaxf(__fsub_rn(my, radii), 0.0f), (float)(H-1));
        float rmaxx = fminf(fmaxf(__fadd_rn(mx, radii), 0.0f), (float)(W-1));
        float rmaxy = fminf(fmaxf(__fadd_rn(my, radii), 0.0f), (float)(H-1));

        float inv = __fdiv_rn(1.0f, det);
        const float L = -0.72134752044448170368f;  // -0.5*log2(e)
        float ca = __fmul_rn(c11, inv) * L;                                   // A' < 0
        float cc = __fmul_rn(c00, inv) * L;                                   // C' < 0
        float cb = __fadd_rn(__fmul_rn(-c01, inv), __fmul_rn(-c10, inv)) * L; // B'

        float dep = depths[i];
        float ol2 = lg2f(opacity[i]);

        // exact dx-maximized bound: pw <= E'*dy^2 + ol2
        float E  = cc - (cb * cb) / (4.0f * ca);          // <= C' < 0
        float Rr = sqrtf(fmaxf(0.0f, (SKIP_L2 - 1.0f - ol2) / E));

        unsigned int db = __float_as_uint(dep);
        unsigned long long key = ((unsigned long long)db << 32) | (unsigned int)i;
        g_key[i] = key;

        int bk = (int)((dep - 0.19f) * 800.0f);
        bk = max(0, min(NB - 1, bk));
        g_bucket[i] = bk;
        int slot = atomicAdd(&g_bucketCnt[bk], 1);
        if (slot < CAP) g_bkey[bk * CAP + slot] = key;

        g_u1[i] = make_float4(mx, ca, cb, cc);
        g_uT[i] = make_float4(my, E, ol2, 0.0f);
        g_u3[i] = make_float4(color[3*i+0], color[3*i+1], color[3*i+2], dep);
        g_u4[i] = make_float4(rminx, rminy, rmaxx, rmaxy);
        g_u5[i] = make_float2(my - Rr, my + Rr);
    }
    grid_barrier();

    // ===== Phase B: redundant per-block bucket scan + rank + scatter =====
    {
        int base = tid * (NB / BLOCK);     // 8 buckets per thread
        int c[NB / BLOCK];
        int s = 0;
        #pragma unroll
        for (int k = 0; k < NB / BLOCK; ++k) { c[k] = g_bucketCnt[base + k]; s += c[k]; }
        int incl = wscan_incl(s, lane);
        if (lane == 31) swsum[warp] = incl;
        __syncthreads();
        if (warp == 0) {
            int v = swsum[lane];
            int iv = wscan_incl(v, lane);
            swsum[lane] = iv - v;
        }
        __syncthreads();
        int e = swsum[warp] + incl - s;
        #pragma unroll
        for (int k = 0; k < NB / BLOCK; ++k) { sOff[base + k] = e; e += c[k]; }
        __syncthreads();

        if (gt < n) {
            int i = gt;
            int bk = g_bucket[i];
            unsigned long long ki = g_key[i];
            int cnt = min(g_bucketCnt[bk], CAP);
            // fully unrolled, predicated: all CAP loads issue in parallel (MLP)
            const ulonglong2* kb2 = (const ulonglong2*)&g_bkey[bk * CAP];
            int r = sOff[bk];
            #pragma unroll
            for (int j2 = 0; j2 < CAP / 2; ++j2) {
                ulonglong2 kk = kb2[j2];
                r += (2 * j2     < cnt && kk.x < ki);
                r += (2 * j2 + 1 < cnt && kk.y < ki);
            }
            g_s1[r] = g_u1[i];
            g_sT[r] = g_uT[i];
            g_s3[r] = g_u3[i];
            g_s4[r] = g_u4[i];
            g_s5[r] = g_u5[i];
        }
    }
    grid_barrier();

    // ---- blocks 256..295: zero bucket counters for next replay, exit ----
    if (b >= NLIST) {
        int idx = (b - NLIST) * BLOCK + tid;
        if (idx < NB) g_bucketCnt[idx] = 0;
        return;
    }

    // ===== Phase C: build list for (tile, slab) = (b>>4, b&15) =====
    const int tile = b >> 4;
    const int slab = b & 15;                    // 2-row slab
    const float sy0 = (float)((tile >> 2) * TILE + slab * 2);
    const float sy1 = sy0 + 1.0f;
    int listCnt;
    {
        // count + ballot cache; warp w handles chunks w and w+32
        for (int chunk = warp; chunk < nch; chunk += 32) {
            int cnt = 0;
            #pragma unroll
            for (int s = 0; s < 8; ++s) {
                int i = chunk * 256 + s * 32 + lane;
                bool m = false;
                if (i < n) {
                    float4 r4 = g_s4[i];
                    float2 yy = g_s5[i];
                    m = tile_mask(r4, tile) && (yy.y >= sy0) && (yy.x <= sy1);
                }
                unsigned ball = __ballot_sync(0xffffffffu, m);
                if (lane == 0) sball[chunk * 8 + s] = ball;
                cnt += __popc(ball);
            }
            if (lane == 0) schcnt[chunk] = cnt;
        }
        __syncthreads();
        if (warp == 0) {
            int a  = (lane < nch) ? schcnt[lane] : 0;
            int b2 = (32 + lane < nch) ? schcnt[32 + lane] : 0;
            int sA = wscan_incl(a, lane);
            int tA = __shfl_sync(0xffffffffu, sA, 31);
            int sB = wscan_incl(b2, lane);
            int tB = __shfl_sync(0xffffffffu, sB, 31);
            if (lane < nch)      schoff[lane]      = sA - a;
            if (32 + lane < nch) schoff[32 + lane] = tA + sB - b2;
            if (lane == 0)       schoff[63]        = tA + tB;   // total
        }
        __syncthreads();
        listCnt = min(schoff[63], CAPQ);
        for (int chunk = warp; chunk < nch; chunk += 32) {
            int off = schoff[chunk];
            #pragma unroll
            for (int s = 0; s < 8; ++s) {
                unsigned ball = sball[chunk * 8 + s];
                if (ball & (1u << lane)) {
                    int i = chunk * 256 + s * 32 + lane;
                    int pos = off + __popc(ball & ((1u << lane) - 1u));
                    if (pos < CAPQ) {
                        g_q1[b][pos] = g_s1[i];
                        g_qT[b][pos] = g_sT[i];
                        g_q3[b][pos] = g_s3[i];
                    }
                }
                off += __popc(ball);
            }
        }
    }
    __syncthreads();

    // ===== Phase D: render 64 px x 16 depth segments =====
    {
        int seg = tid >> 6;                // 0..15 front-to-back segments
        int l   = tid & 63;                // pixel within 32x2 slab
        int px = (tile & 3) * TILE + (l & 31);
        int py = (tile >> 2) * TILE + slab * 2 + (l >> 5);
        float fx = (float)px;
        float fy = (float)py;

        int cnt = listCnt;
        int q   = (cnt + NSEG - 1) >> 4;
        int sbeg = seg * q;
        int send = min(cnt, sbeg + q);

        float T = 1.0f;
        float cr = 0.0f, cg = 0.0f, cbl = 0.0f, cd = 0.0f;

        for (int base = 0; base < q; base += BATCH) {
            {
                int mload = send - (sbeg + base);
                int gidx  = sbeg + base + l;
                if (l < mload && l < BATCH) {
                    sb1[seg * BATCH + l] = g_q1[b][gidx];
                    sbT[seg * BATCH + l] = g_qT[b][gidx];
                    sb3[seg * BATCH + l] = g_q3[b][gidx];
                } else if (l < BATCH) {
                    sbT[seg * BATCH + l] = make_float4(0.f, 0.f, -1.0e9f, 0.f);
                }
            }
            __syncthreads();

            int m = min(BATCH, send - (sbeg + base));
            if (m > 0 && T >= TERM_T) {
                for (int k = 0; k < m; ++k) {
                    float4 pt = sbT[seg * BATCH + k];     // my, E', ol2
                    float dy = fy - pt.x;
                    float rt = fmaf(pt.y * dy, dy, pt.z); // warp-uniform row bound
                    if (rt > SKIP_L2) {
                        float4 p1 = sb1[seg * BATCH + k]; // mx, A', B', C'
                        float dx = fx - p1.x;
                        float u  = p1.z * dy;
                        float v  = fmaf(p1.w * dy, dy, pt.z);
                        float pw = fmaf(fmaf(p1.y, dx, u), dx, v);
                        if (pw > SKIP_L2) {
                            float alpha = fminf(ex2f(pw), 0.99f);
                            float wgt = T * alpha;
                            float4 p3 = sb3[seg * BATCH + k];
                            cr  = fmaf(wgt, p3.x, cr);
                            cg  = fmaf(wgt, p3.y, cg);
                            cbl = fmaf(wgt, p3.z, cbl);
                            cd  = fmaf(wgt, p3.w, cd);
                            T  -= wgt;
                        }
                    }
                }
            }
            if (__syncthreads_and(T < TERM_T)) break;
        }

        // fold 16 depth segments front-to-back: c = cF + TF*cB, T = TF*TB
        __syncthreads();                   // batches dead; alias fold buffer
        pres[0 * BLOCK + tid] = cr;  pres[1 * BLOCK + tid] = cg;
        pres[2 * BLOCK + tid] = cbl; pres[3 * BLOCK + tid] = cd;
        pres[4 * BLOCK + tid] = T;
        __syncthreads();
        if (tid < 64) {
            float crO = pres[0 * BLOCK + tid + 15 * 64];
            float cgO = pres[1 * BLOCK + tid + 15 * 64];
            float cbO = pres[2 * BLOCK + tid + 15 * 64];
            float cdO = pres[3 * BLOCK + tid + 15 * 64];
            float TO  = pres[4 * BLOCK + tid + 15 * 64];
            #pragma unroll
            for (int s = 14; s >= 0; --s) {
                int o = tid + s * 64;
                float Tf = pres[4 * BLOCK + o];
                crO = fmaf(Tf, crO, pres[0 * BLOCK + o]);
                cgO = fmaf(Tf, cgO, pres[1 * BLOCK + o]);
                cbO = fmaf(Tf, cbO, pres[2 * BLOCK + o]);
                cdO = fmaf(Tf, cdO, pres[3 * BLOCK + o]);
                TO *= Tf;
            }
            int pix = py * W + px;
            out[pix * 3 + 0]     = crO + TO;
            out[pix * 3 + 1]     = cgO + TO;
            out[pix * 3 + 2]     = cbO + TO;
            out[H * W * 3 + pix] = cdO;
            out[H * W * 4 + pix] = 1.0f - TO;
        }
    }
}

// ---------------- launch ----------------
extern "C" void kernel_launch(void* const* d_in, const int* in_sizes, int n_in,
                              void* d_out, int out_size)
{
    const float* means   = (const float*)d_in[0];
    const float* cov     = (const float*)d_in[1];
    const float* color   = (const float*)d_in[2];
    const float* opacity = (const float*)d_in[3];
    const float* depths  = (const float*)d_in[4];
    int n = in_sizes[4];
    if (n > MAXN) n = MAXN;

    mega_kernel<<<GRID, BLOCK>>>(means, cov, color, opacity, depths, n, (float*)d_out);
}

// round 14
// speedup vs baseline: 1.3286x; 1.2705x over previous
#include <cuda_runtime.h>
#include <math.h>

#define H 128
#define W 128
#define TILE 32
#define MAXN 16384
#define NB 8192
#define CAP 16
#define GRID 296
#define BLOCK 1024
#define TERM_T 1.0e-8f
#define SKIP_L2 -23.25f   // log2(1e-7); below this alpha < 1e-7
#define BATCH 64
#define NSEG 16
#define NLIST 256         // 16 tiles x 16 two-row slabs
#define CAPQ 2048

__device__ __forceinline__ float ex2f(float x) {
    float y; asm("ex2.approx.ftz.f32 %0, %1;" : "=f"(y) : "f"(x)); return y;
}
__device__ __forceinline__ float lg2f(float x) {
    float y; asm("lg2.approx.f32 %0, %1;" : "=f"(y) : "f"(x)); return y;
}

// ---------------- scratch (device globals; zero-initialized at load) --------
__device__ unsigned long long g_key [MAXN];
__device__ int                g_bucket[MAXN];
__device__ int                g_bucketCnt[NB];     // re-zeroed each run
__device__ unsigned long long g_bkey[NB * CAP];

__device__ float4 g_u1[MAXN];   // mx, A', B', C'   (conic * -0.5*log2 e)
__device__ float4 g_uT[MAXN];   // my, E', log2(op), -
__device__ float4 g_u3[MAXN];   // colR, colG, colB, depth
__device__ float4 g_u5[MAXN];   // ylo, yhi, tilemask16 (bits), -

__device__ float4 g_s1[MAXN];   // depth-sorted
__device__ float4 g_sT[MAXN];
__device__ float4 g_s3[MAXN];
__device__ float4 g_s5[MAXN];

__device__ int g_qi[NLIST][CAPQ];   // per-(tile,slab) index lists

// ---------------- grid barrier (monotone generations, replay-safe) ----------
__device__ unsigned g_arrive = 0;
__device__ volatile unsigned g_release = 0;

__device__ __forceinline__ void grid_barrier()
{
    __syncthreads();
    if (threadIdx.x == 0) {
        __threadfence();
        unsigned old = atomicAdd(&g_arrive, 1u);
        unsigned target = old / GRID + 1u;
        if ((old % GRID) == GRID - 1u) {
            atomicAdd((unsigned*)&g_release, 1u);
        } else {
            while (g_release < target) { }
        }
        __threadfence();
    }
    __syncthreads();
}

__device__ __forceinline__ int wscan_incl(int v, int lane)
{
    #pragma unroll
    for (int d = 1; d < 32; d <<= 1) {
        int u = __shfl_up_sync(0xffffffffu, v, d);
        if (lane >= d) v += u;
    }
    return v;
}

// ---------------- the whole pipeline in ONE kernel ----------------
__global__ void __launch_bounds__(BLOCK, 2) mega_kernel(
    const float* __restrict__ means,
    const float* __restrict__ cov,
    const float* __restrict__ color,
    const float* __restrict__ opacity,
    const float* __restrict__ depths,
    int n, float* __restrict__ out)
{
    const int tid  = threadIdx.x;
    const int b    = blockIdx.x;
    const int lane = tid & 31;
    const int warp = tid >> 5;
    const int gt   = b * BLOCK + tid;
    const int nch  = (n + 255) >> 8;

    // aliased smem arena (uses are time-separated)
    __shared__ __align__(16) char smem_raw[49152];   // 48 KB
    int*      sOff   = (int*)smem_raw;                         // B: 32 KB
    int*      swsum  = (int*)(smem_raw + 32768);               // B: 128 B
    unsigned* sball  = (unsigned*)smem_raw;                    // C: 2 KB
    int*      schcnt = (int*)(smem_raw + 2048);                // C
    int*      schoff = (int*)(smem_raw + 2560);                // C
    float4*   sb1    = (float4*)smem_raw;                      // D: 16 KB
    float4*   sbT    = (float4*)(smem_raw + 16384);            // D: 16 KB
    float4*   sb3    = (float4*)(smem_raw + 32768);            // D: 16 KB
    float*    pres   = (float*)smem_raw;                       // D fold: 20 KB

    // ================= Phase A: preprocess + bucket place =================
    if (gt < n) {
        int i = gt;
        float2 mv  = ((const float2*)means)[i];
        float4 cv  = ((const float4*)cov)[i];
        float mx  = mv.x, my = mv.y;
        float c00 = cv.x, c01 = cv.y, c10 = cv.z, c11 = cv.w;

        // match JAX sequencing for the mask-critical radii math
        float det = __fsub_rn(__fmul_rn(c00, c11), __fmul_rn(c01, c10));
        float mid = __fmul_rn(0.5f, __fadd_rn(c00, c11));
        float s   = sqrtf(fmaxf(__fsub_rn(__fmul_rn(mid, mid), det), 0.1f));
        float lam = fmaxf(__fadd_rn(mid, s), __fsub_rn(mid, s));
        float radii = __fmul_rn(3.0f, ceilf(sqrtf(lam)));

        float rminx = fminf(fmaxf(__fsub_rn(mx, radii), 0.0f), (float)(W-1));
        float rminy = fminf(fmaxf(__fsub_rn(my, radii), 0.0f), (float)(H-1));
        float rmaxx = fminf(fmaxf(__fadd_rn(mx, radii), 0.0f), (float)(W-1));
        float rmaxy = fminf(fmaxf(__fadd_rn(my, radii), 0.0f), (float)(H-1));

        // exact per-tile mask bits (same float ops as reference's tile test)
        unsigned mask16 = 0;
        #pragma unroll
        for (int r = 0; r < 4; ++r) {
            bool yo = fminf(rmaxy, (float)(r * 32 + 31)) > fmaxf(rminy, (float)(r * 32));
            #pragma unroll
            for (int c = 0; c < 4; ++c) {
                bool xo = fminf(rmaxx, (float)(c * 32 + 31)) > fmaxf(rminx, (float)(c * 32));
                mask16 |= (unsigned)(xo && yo) << (r * 4 + c);
            }
        }

        float inv = __fdiv_rn(1.0f, det);
        const float L = -0.72134752044448170368f;  // -0.5*log2(e)
        float ca = __fmul_rn(c11, inv) * L;                                   // A' < 0
        float cc = __fmul_rn(c00, inv) * L;                                   // C' < 0
        float cb = __fadd_rn(__fmul_rn(-c01, inv), __fmul_rn(-c10, inv)) * L; // B'

        float dep = depths[i];
        float ol2 = lg2f(opacity[i]);

        // exact dx-maximized bound: pw <= E'*dy^2 + ol2
        float E  = cc - (cb * cb) / (4.0f * ca);          // <= C' < 0
        float Rr = sqrtf(fmaxf(0.0f, (SKIP_L2 - 1.0f - ol2) / E));

        unsigned int db = __float_as_uint(dep);
        unsigned long long key = ((unsigned long long)db << 32) | (unsigned int)i;
        g_key[i] = key;

        int bk = (int)((dep - 0.19f) * 800.0f);
        bk = max(0, min(NB - 1, bk));
        g_bucket[i] = bk;
        int slot = atomicAdd(&g_bucketCnt[bk], 1);
        if (slot < CAP) g_bkey[bk * CAP + slot] = key;

        g_u1[i] = make_float4(mx, ca, cb, cc);
        g_uT[i] = make_float4(my, E, ol2, 0.0f);
        g_u3[i] = make_float4(color[3*i+0], color[3*i+1], color[3*i+2], dep);
        g_u5[i] = make_float4(my - Rr, my + Rr, __uint_as_float(mask16), 0.0f);
    }
    grid_barrier();

    // ===== Phase B: redundant per-block bucket scan + rank + scatter =====
    {
        int base = tid * (NB / BLOCK);     // 8 buckets per thread
        const int4* bc4 = (const int4*)&g_bucketCnt[base];
        int4 v0 = bc4[0];
        int4 v1 = bc4[1];
        int c[NB / BLOCK] = {v0.x, v0.y, v0.z, v0.w, v1.x, v1.y, v1.z, v1.w};
        int s = c[0]+c[1]+c[2]+c[3]+c[4]+c[5]+c[6]+c[7];
        int incl = wscan_incl(s, lane);
        if (lane == 31) swsum[warp] = incl;
        __syncthreads();
        if (warp == 0) {
            int v = swsum[lane];
            int iv = wscan_incl(v, lane);
            swsum[lane] = iv - v;
        }
        __syncthreads();
        int e = swsum[warp] + incl - s;
        #pragma unroll
        for (int k = 0; k < NB / BLOCK; ++k) { sOff[base + k] = e; e += c[k]; }
        __syncthreads();

        if (gt < n) {
            int i = gt;
            int bk = g_bucket[i];
            unsigned long long ki = g_key[i];
            int cnt = min(g_bucketCnt[bk], CAP);
            // fully unrolled, predicated: all CAP loads issue in parallel
            const ulonglong2* kb2 = (const ulonglong2*)&g_bkey[bk * CAP];
            int r = sOff[bk];
            #pragma unroll
            for (int j2 = 0; j2 < CAP / 2; ++j2) {
                ulonglong2 kk = kb2[j2];
                r += (2 * j2     < cnt && kk.x < ki);
                r += (2 * j2 + 1 < cnt && kk.y < ki);
            }
            g_s1[r] = g_u1[i];
            g_sT[r] = g_uT[i];
            g_s3[r] = g_u3[i];
            g_s5[r] = g_u5[i];
        }
    }
    grid_barrier();

    // ---- blocks 256..295: zero bucket counters for next replay, exit ----
    if (b >= NLIST) {
        int idx = (b - NLIST) * BLOCK + tid;
        if (idx < NB) g_bucketCnt[idx] = 0;
        return;
    }

    // ===== Phase C: build index list for (tile, slab) = (b>>4, b&15) =====
    const int tile = b >> 4;
    const int slab = b & 15;                    // 2-row slab
    const float sy0 = (float)((tile >> 2) * TILE + slab * 2);
    const float sy1 = sy0 + 1.0f;
    int listCnt;
    {
        for (int chunk = warp; chunk < nch; chunk += 32) {
            int cnt = 0;
            #pragma unroll
            for (int s = 0; s < 8; ++s) {
                int i = chunk * 256 + s * 32 + lane;
                bool m = false;
                if (i < n) {
                    float4 y5 = g_s5[i];            // ylo, yhi, mask16
                    unsigned msk = __float_as_uint(y5.z);
                    m = ((msk >> tile) & 1u) && (y5.y >= sy0) && (y5.x <= sy1);
                }
                unsigned ball = __ballot_sync(0xffffffffu, m);
                if (lane == 0) sball[chunk * 8 + s] = ball;
                cnt += __popc(ball);
            }
            if (lane == 0) schcnt[chunk] = cnt;
        }
        __syncthreads();
        if (warp == 0) {
            int a  = (lane < nch) ? schcnt[lane] : 0;
            int b2 = (32 + lane < nch) ? schcnt[32 + lane] : 0;
            int sA = wscan_incl(a, lane);
            int tA = __shfl_sync(0xffffffffu, sA, 31);
            int sB = wscan_incl(b2, lane);
            int tB = __shfl_sync(0xffffffffu, sB, 31);
            if (lane < nch)      schoff[lane]      = sA - a;
            if (32 + lane < nch) schoff[32 + lane] = tA + sB - b2;
            if (lane == 0)       schoff[63]        = tA + tB;   // total
        }
        __syncthreads();
        listCnt = min(schoff[63], CAPQ);
        for (int chunk = warp; chunk < nch; chunk += 32) {
            int off = schoff[chunk];
            #pragma unroll
            for (int s = 0; s < 8; ++s) {
                unsigned ball = sball[chunk * 8 + s];
                if (ball & (1u << lane)) {
                    int pos = off + __popc(ball & ((1u << lane) - 1u));
                    if (pos < CAPQ)
                        g_qi[b][pos] = chunk * 256 + s * 32 + lane;
                }
                off += __popc(ball);
            }
        }
    }
    __syncthreads();

    // ===== Phase D: render 64 px x 16 depth segments (branchless core) =====
    {
        int seg = tid >> 6;                // 0..15 front-to-back segments
        int l   = tid & 63;                // pixel within 32x2 slab
        int px = (tile & 3) * TILE + (l & 31);
        int py = (tile >> 2) * TILE + slab * 2 + (l >> 5);
        float fx = (float)px;
        float fy = (float)py;

        int cnt = listCnt;
        int q   = (cnt + NSEG - 1) >> 4;
        int sbeg = seg * q;
        int send = min(cnt, sbeg + q);

        float T = 1.0f;
        float cr = 0.0f, cg = 0.0f, cbl = 0.0f, cd = 0.0f;

        for (int base = 0; base < q; base += BATCH) {
            {
                int mload = send - (sbeg + base);
                if (l < BATCH) {
                    int sidx = seg * BATCH + l;
                    if (l < mload) {
                        int gi = g_qi[b][sbeg + base + l];
                        sb1[sidx] = g_s1[gi];
                        sbT[sidx] = g_sT[gi];
                        sb3[sidx] = g_s3[gi];
                    } else {
                        sb1[sidx] = make_float4(0.f, 0.f, 0.f, 0.f);
                        sbT[sidx] = make_float4(0.f, 0.f, -1.0e9f, 0.f);
                        sb3[sidx] = make_float4(0.f, 0.f, 0.f, 0.f);
                    }
                }
            }
            __syncthreads();

            int m = min(BATCH, send - (sbeg + base));
            if (m > 0 && T >= TERM_T) {
                #pragma unroll 4
                for (int k = 0; k < m; ++k) {
                    float4 p1 = sb1[seg * BATCH + k]; // mx, A', B', C'
                    float4 pt = sbT[seg * BATCH + k]; // my, -, ol2
                    float dx = fx - p1.x;
                    float dy = fy - pt.x;
                    float t2 = fmaf(p1.y, dx, p1.z * dy);
                    float t1 = fmaf(p1.w * dy, dy, pt.z);
                    float pw = fmaf(t2, dx, t1);      // log2(gw*op)
                    float alpha = (pw > SKIP_L2) ? fminf(ex2f(pw), 0.99f) : 0.0f;
                    float wgt = T * alpha;
                    float4 p3 = sb3[seg * BATCH + k];
                    cr  = fmaf(wgt, p3.x, cr);
                    cg  = fmaf(wgt, p3.y, cg);
                    cbl = fmaf(wgt, p3.z, cbl);
                    cd  = fmaf(wgt, p3.w, cd);
                    T  -= wgt;
                }
            }
            if (__syncthreads_and(T < TERM_T)) break;
        }

        // fold 16 depth segments front-to-back: c = cF + TF*cB, T = TF*TB
        __syncthreads();                   // batches dead; alias fold buffer
        pres[0 * BLOCK + tid] = cr;  pres[1 * BLOCK + tid] = cg;
        pres[2 * BLOCK + tid] = cbl; pres[3 * BLOCK + tid] = cd;
        pres[4 * BLOCK + tid] = T;
        __syncthreads();
        if (tid < 64) {
            float crO = pres[0 * BLOCK + tid + 15 * 64];
            float cgO = pres[1 * BLOCK + tid + 15 * 64];
            float cbO = pres[2 * BLOCK + tid + 15 * 64];
            float cdO = pres[3 * BLOCK + tid + 15 * 64];
            float TO  = pres[4 * BLOCK + tid + 15 * 64];
            #pragma unroll
            for (int s = 14; s >= 0; --s) {
                int o = tid + s * 64;
                float Tf = pres[4 * BLOCK + o];
                crO = fmaf(Tf, crO, pres[0 * BLOCK + o]);
                cgO = fmaf(Tf, cgO, pres[1 * BLOCK + o]);
                cbO = fmaf(Tf, cbO, pres[2 * BLOCK + o]);
                cdO = fmaf(Tf, cdO, pres[3 * BLOCK + o]);
                TO *= Tf;
            }
            int pix = py * W + px;
            out[pix * 3 + 0]     = crO + TO;
            out[pix * 3 + 1]     = cgO + TO;
            out[pix * 3 + 2]     = cbO + TO;
            out[H * W * 3 + pix] = cdO;
            out[H * W * 4 + pix] = 1.0f - TO;
        }
    }
}

// ---------------- launch ----------------
extern "C" void kernel_launch(void* const* d_in, const int* in_sizes, int n_in,
                              void* d_out, int out_size)
{
    const float* means   = (const float*)d_in[0];
    const float* cov     = (const float*)d_in[1];
    const float* color   = (const float*)d_in[2];
    const float* opacity = (const float*)d_in[3];
    const float* depths  = (const float*)d_in[4];
    int n = in_sizes[4];
    if (n > MAXN) n = MAXN;

    mega_kernel<<<GRID, BLOCK>>>(means, cov, color, opacity, depths, n, (float*)d_out);
}

// round 15
// speedup vs baseline: 1.3478x; 1.0145x over previous
#include <cuda_runtime.h>
#include <math.h>

#define H 128
#define W 128
#define TILE 32
#define MAXN 16384
#define NB 8192
#define CAP 16
#define GRID 296
#define BLOCK 1024
#define TERM_T 1.0e-8f
#define SKIP_L2 -23.25f   // log2(1e-7); below this alpha < 1e-7
#define BATCH 64
#define NSEG 16
#define NLIST 256         // 16 tiles x 16 two-row slabs
#define TCAP 4096
#define SCAP 2048
#define SMEM_BYTES 57600

__device__ __forceinline__ float ex2f(float x) {
    float y; asm("ex2.approx.ftz.f32 %0, %1;" : "=f"(y) : "f"(x)); return y;
}
__device__ __forceinline__ float lg2f(float x) {
    float y; asm("lg2.approx.f32 %0, %1;" : "=f"(y) : "f"(x)); return y;
}

// ---------------- scratch (device globals; zero-initialized at load) --------
__device__ unsigned long long g_key [MAXN];
__device__ int                g_bucket[MAXN];
__device__ int                g_bucketCnt[NB];     // re-zeroed each run
__device__ unsigned long long g_bkey[NB * CAP];

__device__ float4         g_u1[MAXN];   // mx, A', B', C'  (conic * -0.5*log2 e)
__device__ float4         g_uT[MAXN];   // my, -, ol2, -
__device__ float4         g_u3[MAXN];   // colR, colG, colB, depth
__device__ float2         g_uyw[MAXN];  // y-significance window
__device__ unsigned short g_uM[MAXN];   // 16-bit tile mask

__device__ float4         g_s1[MAXN];   // depth-sorted
__device__ float4         g_sT[MAXN];
__device__ float4         g_s3[MAXN];
__device__ float2         g_yw[MAXN];
__device__ unsigned short g_m16s[MAXN];

__device__ int g_ti[16][TCAP];          // per-tile index lists
__device__ int g_tileCnt[16];

// ---------------- grid barrier (monotone generations, replay-safe) ----------
__device__ unsigned g_arrive = 0;
__device__ volatile unsigned g_release = 0;

__device__ __forceinline__ void grid_barrier()
{
    __syncthreads();
    if (threadIdx.x == 0) {
        __threadfence();
        unsigned old = atomicAdd(&g_arrive, 1u);
        unsigned target = old / GRID + 1u;
        if ((old % GRID) == GRID - 1u) {
            atomicAdd((unsigned*)&g_release, 1u);
        } else {
            while (g_release < target) { }
        }
        __threadfence();
    }
    __syncthreads();
}

__device__ __forceinline__ int wscan_incl(int v, int lane)
{
    #pragma unroll
    for (int d = 1; d < 32; d <<= 1) {
        int u = __shfl_up_sync(0xffffffffu, v, d);
        if (lane >= d) v += u;
    }
    return v;
}

// ---------------- the whole pipeline in ONE kernel ----------------
__global__ void __launch_bounds__(BLOCK, 2) mega_kernel(
    const float* __restrict__ means,
    const float* __restrict__ cov,
    const float* __restrict__ color,
    const float* __restrict__ opacity,
    const float* __restrict__ depths,
    int n, float* __restrict__ out)
{
    const int tid  = threadIdx.x;
    const int b    = blockIdx.x;
    const int lane = tid & 31;
    const int warp = tid >> 5;
    const int gt   = b * BLOCK + tid;

    extern __shared__ __align__(16) char smem_raw[];
    int*    sOff  = (int*)smem_raw;                      // B: 32 KB
    int*    swc   = (int*)(smem_raw + 32768);            // scans: 128 B
    int*    swe   = (int*)(smem_raw + 32896);            // 128 B
    int*    swt   = (int*)(smem_raw + 33024);            // 4 B
    float4* sb1   = (float4*)smem_raw;                   // D: 16 KB
    float4* sbT   = (float4*)(smem_raw + 16384);         // D: 16 KB
    float4* sb3   = (float4*)(smem_raw + 32768);         // D: 16 KB
    float*  pres  = (float*)smem_raw;                    // fold: 20 KB
    int*    slist = (int*)(smem_raw + 49152);            // slab list: 8 KB

    // ================= Phase A: preprocess + bucket place =================
    if (gt < n) {
        int i = gt;
        float2 mv  = ((const float2*)means)[i];
        float4 cv  = ((const float4*)cov)[i];
        float mx  = mv.x, my = mv.y;
        float c00 = cv.x, c01 = cv.y, c10 = cv.z, c11 = cv.w;

        // match JAX sequencing for the mask-critical radii math
        float det = __fsub_rn(__fmul_rn(c00, c11), __fmul_rn(c01, c10));
        float mid = __fmul_rn(0.5f, __fadd_rn(c00, c11));
        float s   = sqrtf(fmaxf(__fsub_rn(__fmul_rn(mid, mid), det), 0.1f));
        float lam = fmaxf(__fadd_rn(mid, s), __fsub_rn(mid, s));
        float radii = __fmul_rn(3.0f, ceilf(sqrtf(lam)));

        float rminx = fminf(fmaxf(__fsub_rn(mx, radii), 0.0f), (float)(W-1));
        float rminy = fminf(fmaxf(__fsub_rn(my, radii), 0.0f), (float)(H-1));
        float rmaxx = fminf(fmaxf(__fadd_rn(mx, radii), 0.0f), (float)(W-1));
        float rmaxy = fminf(fmaxf(__fadd_rn(my, radii), 0.0f), (float)(H-1));

        // exact per-tile mask bits (same float ops as reference's tile test)
        unsigned mask16 = 0;
        #pragma unroll
        for (int r = 0; r < 4; ++r) {
            bool yo = fminf(rmaxy, (float)(r * 32 + 31)) > fmaxf(rminy, (float)(r * 32));
            #pragma unroll
            for (int c = 0; c < 4; ++c) {
                bool xo = fminf(rmaxx, (float)(c * 32 + 31)) > fmaxf(rminx, (float)(c * 32));
                mask16 |= (unsigned)(xo && yo) << (r * 4 + c);
            }
        }

        float inv = __fdiv_rn(1.0f, det);
        const float L = -0.72134752044448170368f;  // -0.5*log2(e)
        float ca = __fmul_rn(c11, inv) * L;                                   // A' < 0
        float cc = __fmul_rn(c00, inv) * L;                                   // C' < 0
        float cb = __fadd_rn(__fmul_rn(-c01, inv), __fmul_rn(-c10, inv)) * L; // B'

        float dep = depths[i];
        float ol2 = lg2f(opacity[i]);

        // exact dx-maximized bound: pw <= E'*dy^2 + ol2
        float E  = cc - (cb * cb) / (4.0f * ca);
        float Rr = sqrtf(fmaxf(0.0f, (SKIP_L2 - 1.0f - ol2) / E));

        unsigned int db = __float_as_uint(dep);
        unsigned long long key = ((unsigned long long)db << 32) | (unsigned int)i;
        g_key[i] = key;

        int bk = (int)((dep - 0.19f) * 800.0f);
        bk = max(0, min(NB - 1, bk));
        g_bucket[i] = bk;
        int slot = atomicAdd(&g_bucketCnt[bk], 1);
        if (slot < CAP) g_bkey[bk * CAP + slot] = key;

        g_u1[i]  = make_float4(mx, ca, cb, cc);
        g_uT[i]  = make_float4(my, E, ol2, 0.0f);
        g_u3[i]  = make_float4(color[3*i+0], color[3*i+1], color[3*i+2], dep);
        g_uyw[i] = make_float2(my - Rr, my + Rr);
        g_uM[i]  = (unsigned short)mask16;
    }
    grid_barrier();

    // ===== Phase B: redundant per-block bucket scan + rank + scatter =====
    {
        int base = tid * (NB / BLOCK);     // 8 buckets per thread
        const int4* bc4 = (const int4*)&g_bucketCnt[base];
        int4 v0 = bc4[0];
        int4 v1 = bc4[1];
        int c[NB / BLOCK] = {v0.x, v0.y, v0.z, v0.w, v1.x, v1.y, v1.z, v1.w};
        int s = c[0]+c[1]+c[2]+c[3]+c[4]+c[5]+c[6]+c[7];
        int incl = wscan_incl(s, lane);
        if (lane == 31) swc[warp] = incl;
        __syncthreads();
        if (warp == 0) {
            int v = swc[lane];
            int iv = wscan_incl(v, lane);
            swc[lane] = iv - v;
        }
        __syncthreads();
        int e = swc[warp] + incl - s;
        #pragma unroll
        for (int k = 0; k < NB / BLOCK; ++k) { sOff[base + k] = e; e += c[k]; }
        __syncthreads();

        if (gt < n) {
            int i = gt;
            int bk = g_bucket[i];
            unsigned long long ki = g_key[i];
            int cnt = min(g_bucketCnt[bk], CAP);
            const ulonglong2* kb2 = (const ulonglong2*)&g_bkey[bk * CAP];
            int r = sOff[bk];
            #pragma unroll
            for (int j2 = 0; j2 < CAP / 2; ++j2) {
                ulonglong2 kk = kb2[j2];
                r += (2 * j2     < cnt && kk.x < ki);
                r += (2 * j2 + 1 < cnt && kk.y < ki);
            }
            g_s1[r]   = g_u1[i];
            g_sT[r]   = g_uT[i];
            g_s3[r]   = g_u3[i];
            g_yw[r]   = g_uyw[i];
            g_m16s[r] = g_uM[i];
        }
    }
    grid_barrier();

    // ---- blocks 256..295: zero bucket counters, hit barrier 3, exit ----
    if (b >= NLIST) {
        int idx = (b - NLIST) * BLOCK + tid;
        if (idx < NB) g_bucketCnt[idx] = 0;
        grid_barrier();
        return;
    }

    // ===== Phase C1 (blocks 0..15): build per-tile index lists =====
    if (b < 16) {
        const int tile8 = b;
        const uint4* mv = (const uint4*)g_m16s;   // 8 packed masks per uint4
        int total = 0;
        #pragma unroll
        for (int r = 0; r < 2; ++r) {
            int tv = r * 1024 + tid;
            int i0 = tv * 8;
            uint4 mm = mv[tv];
            unsigned m8 = 0;
            unsigned ms[8] = {mm.x & 0xffffu, mm.x >> 16, mm.y & 0xffffu, mm.y >> 16,
                              mm.z & 0xffffu, mm.z >> 16, mm.w & 0xffffu, mm.w >> 16};
            #pragma unroll
            for (int k = 0; k < 8; ++k)
                m8 |= (((ms[k] >> tile8) & 1u) && (i0 + k < n)) ? (1u << k) : 0u;
            int cnt = __popc(m8);
            int incl = wscan_incl(cnt, lane);
            if (lane == 31) swc[warp] = incl;
            __syncthreads();
            if (warp == 0) {
                int v = swc[lane];
                int iv = wscan_incl(v, lane);
                swe[lane] = iv - v;
                if (lane == 31) swt[0] = iv;
            }
            __syncthreads();
            int basep = total + swe[warp] + incl - cnt;
            #pragma unroll
            for (int k = 0; k < 8; ++k)
                if (m8 & (1u << k)) {
                    int p = basep + __popc(m8 & ((1u << k) - 1u));
                    if (p < TCAP) g_ti[tile8][p] = i0 + k;
                }
            total += swt[0];
            __syncthreads();
        }
        if (tid == 0) g_tileCnt[tile8] = min(total, TCAP);
    }
    grid_barrier();

    // ===== Phase C2: filter parent tile list into smem slab list =====
    const int tile = b >> 4;
    const int slab = b & 15;                    // 2-row slab
    const float sy0 = (float)((tile >> 2) * TILE + slab * 2);
    const float sy1 = sy0 + 1.0f;
    int listCnt;
    {
        int pcnt = g_tileCnt[tile];
        int4 g4 = ((const int4*)&g_ti[tile][0])[tid];   // 4 entries per thread
        int gi0 = g4.x, gi1 = g4.y, gi2 = g4.z, gi3 = g4.w;
        int j0 = tid * 4;
        float2 y0 = g_yw[gi0];
        float2 y1 = g_yw[gi1];
        float2 y2 = g_yw[gi2];
        float2 y3 = g_yw[gi3];
        unsigned m4 = 0;
        m4 |= (j0 + 0 < pcnt && y0.y >= sy0 && y0.x <= sy1) ? 1u : 0u;
        m4 |= (j0 + 1 < pcnt && y1.y >= sy0 && y1.x <= sy1) ? 2u : 0u;
        m4 |= (j0 + 2 < pcnt && y2.y >= sy0 && y2.x <= sy1) ? 4u : 0u;
        m4 |= (j0 + 3 < pcnt && y3.y >= sy0 && y3.x <= sy1) ? 8u : 0u;
        int cnt = __popc(m4);
        int incl = wscan_incl(cnt, lane);
        if (lane == 31) swc[warp] = incl;
        __syncthreads();
        if (warp == 0) {
            int v = swc[lane];
            int iv = wscan_incl(v, lane);
            swe[lane] = iv - v;
            if (lane == 31) swt[0] = iv;
        }
        __syncthreads();
        int basep = swe[warp] + incl - cnt;
        int gis[4] = {gi0, gi1, gi2, gi3};
        #pragma unroll
        for (int k = 0; k < 4; ++k)
            if (m4 & (1u << k)) {
                int p = basep + __popc(m4 & ((1u << k) - 1u));
                if (p < SCAP) slist[p] = gis[k];
            }
        __syncthreads();
        listCnt = min(swt[0], SCAP);
    }

    // ===== Phase D: render 64 px x 16 depth segments (branchless core) =====
    {
        int seg = tid >> 6;                // 0..15 front-to-back segments
        int l   = tid & 63;                // pixel within 32x2 slab
        int px = (tile & 3) * TILE + (l & 31);
        int py = (tile >> 2) * TILE + slab * 2 + (l >> 5);
        float fx = (float)px;
        float fy = (float)py;

        int cnt = listCnt;
        int q   = (cnt + NSEG - 1) >> 4;
        int sbeg = seg * q;
        int send = min(cnt, sbeg + q);

        float T = 1.0f;
        float cr = 0.0f, cg = 0.0f, cbl = 0.0f, cd = 0.0f;

        for (int base = 0; base < q; base += BATCH) {
            {
                int mload = send - (sbeg + base);
                if (l < BATCH) {
                    int sidx = seg * BATCH + l;
                    if (l < mload) {
                        int gi = slist[sbeg + base + l];
                        sb1[sidx] = g_s1[gi];
                        sbT[sidx] = g_sT[gi];
                        sb3[sidx] = g_s3[gi];
                    } else {
                        sb1[sidx] = make_float4(0.f, 0.f, 0.f, 0.f);
                        sbT[sidx] = make_float4(0.f, 0.f, -1.0e9f, 0.f);
                        sb3[sidx] = make_float4(0.f, 0.f, 0.f, 0.f);
                    }
                }
            }
            __syncthreads();

            int m = min(BATCH, send - (sbeg + base));
            if (m > 0 && T >= TERM_T) {
                #pragma unroll 4
                for (int k = 0; k < m; ++k) {
                    float4 p1 = sb1[seg * BATCH + k]; // mx, A', B', C'
                    float4 pt = sbT[seg * BATCH + k]; // my, -, ol2
                    float dx = fx - p1.x;
                    float dy = fy - pt.x;
                    float t2 = fmaf(p1.y, dx, p1.z * dy);
                    float t1 = fmaf(p1.w * dy, dy, pt.z);
                    float pw = fmaf(t2, dx, t1);      // log2(gw*op)
                    float alpha = (pw > SKIP_L2) ? fminf(ex2f(pw), 0.99f) : 0.0f;
                    float wgt = T * alpha;
                    float4 p3 = sb3[seg * BATCH + k];
                    cr  = fmaf(wgt, p3.x, cr);
                    cg  = fmaf(wgt, p3.y, cg);
                    cbl = fmaf(wgt, p3.z, cbl);
                    cd  = fmaf(wgt, p3.w, cd);
                    T  -= wgt;
                }
            }
            if (__syncthreads_and(T < TERM_T)) break;
        }

        // fold 16 depth segments front-to-back: c = cF + TF*cB, T = TF*TB
        __syncthreads();                   // batches dead; alias fold buffer
        pres[0 * BLOCK + tid] = cr;  pres[1 * BLOCK + tid] = cg;
        pres[2 * BLOCK + tid] = cbl; pres[3 * BLOCK + tid] = cd;
        pres[4 * BLOCK + tid] = T;
        __syncthreads();
        if (tid < 64) {
            float crO = pres[0 * BLOCK + tid + 15 * 64];
            float cgO = pres[1 * BLOCK + tid + 15 * 64];
            float cbO = pres[2 * BLOCK + tid + 15 * 64];
            float cdO = pres[3 * BLOCK + tid + 15 * 64];
            float TO  = pres[4 * BLOCK + tid + 15 * 64];
            #pragma unroll
            for (int s = 14; s >= 0; --s) {
                int o = tid + s * 64;
                float Tf = pres[4 * BLOCK + o];
                crO = fmaf(Tf, crO, pres[0 * BLOCK + o]);
                cgO = fmaf(Tf, cgO, pres[1 * BLOCK + o]);
                cbO = fmaf(Tf, cbO, pres[2 * BLOCK + o]);
                cdO = fmaf(Tf, cdO, pres[3 * BLOCK + o]);
                TO *= Tf;
            }
            int pix = py * W + px;
            out[pix * 3 + 0]     = crO + TO;
            out[pix * 3 + 1]     = cgO + TO;
            out[pix * 3 + 2]     = cbO + TO;
            out[H * W * 3 + pix] = cdO;
            out[H * W * 4 + pix] = 1.0f - TO;
        }
    }
}

// ---------------- launch ----------------
extern "C" void kernel_launch(void* const* d_in, const int* in_sizes, int n_in,
                              void* d_out, int out_size)
{
    const float* means   = (const float*)d_in[0];
    const float* cov     = (const float*)d_in[1];
    const float* color   = (const float*)d_in[2];
    const float* opacity = (const float*)d_in[3];
    const float* depths  = (const float*)d_in[4];
    int n = in_sizes[4];
    if (n > MAXN) n = MAXN;

    static int configured = 0;
    if (!configured) {
        cudaFuncSetAttribute(mega_kernel,
                             cudaFuncAttributeMaxDynamicSharedMemorySize, SMEM_BYTES);
        configured = 1;
    }
    mega_kernel<<<GRID, BLOCK, SMEM_BYTES>>>(means, cov, color, opacity, depths, n,
                                             (float*)d_out);
}

// round 16
// speedup vs baseline: 1.4321x; 1.0626x over previous
#include <cuda_runtime.h>
#include <math.h>

#define H 128
#define W 128
#define TILE 32
#define MAXN 16384
#define NB 8192
#define CAP 16
#define GRID 296
#define BLOCK 1024
#define TERM_T 1.0e-8f
#define SKIP_L2 -23.25f   // log2(1e-7), used only for the y-window radius
#define BATCH 64
#define NSEG 16
#define NLIST 256         // 16 tiles x 16 two-row slabs
#define TCAP 4096
#define SCAP 2048
#define SMEM_BYTES 57600

__device__ __forceinline__ float ex2f(float x) {
    float y; asm("ex2.approx.ftz.f32 %0, %1;" : "=f"(y) : "f"(x)); return y;
}
__device__ __forceinline__ float lg2f(float x) {
    float y; asm("lg2.approx.f32 %0, %1;" : "=f"(y) : "f"(x)); return y;
}

// ---------------- scratch (device globals; zero-initialized at load) --------
__device__ unsigned long long g_key [MAXN];
__device__ int                g_bucket[MAXN];
__device__ int                g_bucketCnt[NB];     // re-zeroed each run
__device__ unsigned long long g_bkey[NB * CAP];

__device__ float4         g_u1[MAXN];   // mx, A', B', C'  (conic * -0.5*log2 e)
__device__ float2         g_uT[MAXN];   // my, ol2
__device__ float4         g_u3[MAXN];   // colR, colG, colB, depth
__device__ float2         g_uyw[MAXN];  // y-significance window
__device__ unsigned short g_uM[MAXN];   // 16-bit tile mask

__device__ float4         g_s1[MAXN];   // depth-sorted
__device__ float2         g_sT[MAXN];
__device__ float4         g_s3[MAXN];
__device__ float2         g_yw[MAXN];
__device__ unsigned short g_m16s[MAXN];

__device__ int g_ti[16][TCAP];          // per-tile index lists
__device__ int g_tileCnt[16];

// ---------------- grid barrier (monotone generations, replay-safe) ----------
__device__ unsigned g_arrive = 0;
__device__ volatile unsigned g_release = 0;

__device__ __forceinline__ void grid_barrier()
{
    __syncthreads();
    if (threadIdx.x == 0) {
        __threadfence();
        unsigned old = atomicAdd(&g_arrive, 1u);
        unsigned target = old / GRID + 1u;
        if ((old % GRID) == GRID - 1u) {
            atomicAdd((unsigned*)&g_release, 1u);
        } else {
            while (g_release < target) { }
        }
        __threadfence();
    }
    __syncthreads();
}

__device__ __forceinline__ int wscan_incl(int v, int lane)
{
    #pragma unroll
    for (int d = 1; d < 32; d <<= 1) {
        int u = __shfl_up_sync(0xffffffffu, v, d);
        if (lane >= d) v += u;
    }
    return v;
}

// ---------------- the whole pipeline in ONE kernel ----------------
__global__ void __launch_bounds__(BLOCK, 2) mega_kernel(
    const float* __restrict__ means,
    const float* __restrict__ cov,
    const float* __restrict__ color,
    const float* __restrict__ opacity,
    const float* __restrict__ depths,
    int n, float* __restrict__ out)
{
    const int tid  = threadIdx.x;
    const int b    = blockIdx.x;
    const int lane = tid & 31;
    const int warp = tid >> 5;
    const int gt   = b * BLOCK + tid;

    extern __shared__ __align__(16) char smem_raw[];
    // layout: [0,32768) sbR | B-scan sOff | fold pres(20KB)
    //         [32768,49152) sb3 | [49152,57344) slist | [57344,57600) scratch
    int*    sOff  = (int*)smem_raw;                      // B: 32 KB
    float4* sbR   = (float4*)smem_raw;                   // D: [2 rows][16 seg][64]
    float4* sb3   = (float4*)(smem_raw + 32768);         // D: 16 KB
    int*    slist = (int*)(smem_raw + 49152);            // slab list: 8 KB
    int*    swc   = (int*)(smem_raw + 57344);            // 128 B
    int*    swe   = (int*)(smem_raw + 57472);            // 128 B
    float*  pres  = (float*)smem_raw;                    // fold: 20 KB

    // ================= Phase A: preprocess + bucket place =================
    if (gt < n) {
        int i = gt;
        float2 mv  = ((const float2*)means)[i];
        float4 cv  = ((const float4*)cov)[i];
        float mx  = mv.x, my = mv.y;
        float c00 = cv.x, c01 = cv.y, c10 = cv.z, c11 = cv.w;

        // match JAX sequencing for the mask-critical radii math
        float det = __fsub_rn(__fmul_rn(c00, c11), __fmul_rn(c01, c10));
        float mid = __fmul_rn(0.5f, __fadd_rn(c00, c11));
        float s   = sqrtf(fmaxf(__fsub_rn(__fmul_rn(mid, mid), det), 0.1f));
        float lam = fmaxf(__fadd_rn(mid, s), __fsub_rn(mid, s));
        float radii = __fmul_rn(3.0f, ceilf(sqrtf(lam)));

        float rminx = fminf(fmaxf(__fsub_rn(mx, radii), 0.0f), (float)(W-1));
        float rminy = fminf(fmaxf(__fsub_rn(my, radii), 0.0f), (float)(H-1));
        float rmaxx = fminf(fmaxf(__fadd_rn(mx, radii), 0.0f), (float)(W-1));
        float rmaxy = fminf(fmaxf(__fadd_rn(my, radii), 0.0f), (float)(H-1));

        // exact per-tile mask bits (same float ops as reference's tile test)
        unsigned mask16 = 0;
        #pragma unroll
        for (int r = 0; r < 4; ++r) {
            bool yo = fminf(rmaxy, (float)(r * 32 + 31)) > fmaxf(rminy, (float)(r * 32));
            #pragma unroll
            for (int c = 0; c < 4; ++c) {
                bool xo = fminf(rmaxx, (float)(c * 32 + 31)) > fmaxf(rminx, (float)(c * 32));
                mask16 |= (unsigned)(xo && yo) << (r * 4 + c);
            }
        }

        float inv = __fdiv_rn(1.0f, det);
        const float L = -0.72134752044448170368f;  // -0.5*log2(e)
        float ca = __fmul_rn(c11, inv) * L;                                   // A' < 0
        float cc = __fmul_rn(c00, inv) * L;                                   // C' < 0
        float cb = __fadd_rn(__fmul_rn(-c01, inv), __fmul_rn(-c10, inv)) * L; // B'

        float dep = depths[i];
        float ol2 = lg2f(opacity[i]);

        // exact dx-maximized bound: pw <= E'*dy^2 + ol2
        float E  = cc - (cb * cb) / (4.0f * ca);
        float Rr = sqrtf(fmaxf(0.0f, (SKIP_L2 - 1.0f - ol2) / E));

        unsigned int db = __float_as_uint(dep);
        unsigned long long key = ((unsigned long long)db << 32) | (unsigned int)i;
        g_key[i] = key;

        int bk = (int)((dep - 0.19f) * 800.0f);
        bk = max(0, min(NB - 1, bk));
        g_bucket[i] = bk;
        int slot = atomicAdd(&g_bucketCnt[bk], 1);
        if (slot < CAP) g_bkey[bk * CAP + slot] = key;

        g_u1[i]  = make_float4(mx, ca, cb, cc);
        g_uT[i]  = make_float2(my, ol2);
        g_u3[i]  = make_float4(color[3*i+0], color[3*i+1], color[3*i+2], dep);
        g_uyw[i] = make_float2(my - Rr, my + Rr);
        g_uM[i]  = (unsigned short)mask16;
    }
    grid_barrier();

    // ===== Phase B: redundant per-block bucket scan + rank + scatter =====
    {
        int base = tid * (NB / BLOCK);     // 8 buckets per thread
        const int4* bc4 = (const int4*)&g_bucketCnt[base];
        int4 v0 = bc4[0];
        int4 v1 = bc4[1];
        int c[NB / BLOCK] = {v0.x, v0.y, v0.z, v0.w, v1.x, v1.y, v1.z, v1.w};
        int s = c[0]+c[1]+c[2]+c[3]+c[4]+c[5]+c[6]+c[7];
        int incl = wscan_incl(s, lane);
        if (lane == 31) swc[warp] = incl;
        __syncthreads();
        if (warp == 0) {
            int v = swc[lane];
            int iv = wscan_incl(v, lane);
            swe[lane] = iv - v;
        }
        __syncthreads();
        int e = swe[warp] + incl - s;
        #pragma unroll
        for (int k = 0; k < NB / BLOCK; ++k) { sOff[base + k] = e; e += c[k]; }
        __syncthreads();

        if (gt < n) {
            int i = gt;
            int bk = g_bucket[i];
            unsigned long long ki = g_key[i];
            int cnt = min(g_bucketCnt[bk], CAP);
            const ulonglong2* kb2 = (const ulonglong2*)&g_bkey[bk * CAP];
            int r = sOff[bk];
            #pragma unroll
            for (int j2 = 0; j2 < CAP / 2; ++j2) {
                ulonglong2 kk = kb2[j2];
                r += (2 * j2     < cnt && kk.x < ki);
                r += (2 * j2 + 1 < cnt && kk.y < ki);
            }
            g_s1[r]   = g_u1[i];
            g_sT[r]   = g_uT[i];
            g_s3[r]   = g_u3[i];
            g_yw[r]   = g_uyw[i];
            g_m16s[r] = g_uM[i];
        }
    }
    grid_barrier();

    // ---- blocks 256..295: zero bucket counters, hit barrier 3, exit ----
    if (b >= NLIST) {
        int idx = (b - NLIST) * BLOCK + tid;
        if (idx < NB) g_bucketCnt[idx] = 0;
        grid_barrier();
        return;
    }

    // ===== Phase C1 (blocks 0..15): build per-tile index lists =====
    if (b < 16) {
        const int tile8 = b;
        const uint4* mv = (const uint4*)g_m16s;   // 8 packed masks per uint4
        int total = 0;
        #pragma unroll
        for (int r = 0; r < 2; ++r) {
            int tv = r * 1024 + tid;
            int i0 = tv * 8;
            uint4 mm = mv[tv];
            unsigned m8 = 0;
            unsigned ms[8] = {mm.x & 0xffffu, mm.x >> 16, mm.y & 0xffffu, mm.y >> 16,
                              mm.z & 0xffffu, mm.z >> 16, mm.w & 0xffffu, mm.w >> 16};
            #pragma unroll
            for (int k = 0; k < 8; ++k)
                m8 |= (((ms[k] >> tile8) & 1u) && (i0 + k < n)) ? (1u << k) : 0u;
            int cnt = __popc(m8);
            int incl = wscan_incl(cnt, lane);
            if (lane == 31) swc[warp] = incl;
            __syncthreads();
            if (warp == 0) {
                int v = swc[lane];
                int iv = wscan_incl(v, lane);
                swe[lane] = iv - v;
            }
            __syncthreads();
            int basep = total + swe[warp] + incl - cnt;
            #pragma unroll
            for (int k = 0; k < 8; ++k)
                if (m8 & (1u << k)) {
                    int p = basep + __popc(m8 & ((1u << k) - 1u));
                    if (p < TCAP) g_ti[tile8][p] = i0 + k;
                }
            total += swe[31] + swc[31];
            __syncthreads();
        }
        if (tid == 0) g_tileCnt[tile8] = min(total, TCAP);
    }
    grid_barrier();

    // ===== Phase C2: filter parent tile list into smem slab list =====
    const int tile = b >> 4;
    const int slab = b & 15;                    // 2-row slab
    const float sy0 = (float)((tile >> 2) * TILE + slab * 2);
    const float sy1 = sy0 + 1.0f;
    int listCnt;
    {
        int pcnt = g_tileCnt[tile];
        int4 g4 = ((const int4*)&g_ti[tile][0])[tid];   // 4 entries per thread
        int gi0 = g4.x, gi1 = g4.y, gi2 = g4.z, gi3 = g4.w;
        int j0 = tid * 4;
        float2 y0 = g_yw[gi0];
        float2 y1 = g_yw[gi1];
        float2 y2 = g_yw[gi2];
        float2 y3 = g_yw[gi3];
        unsigned m4 = 0;
        m4 |= (j0 + 0 < pcnt && y0.y >= sy0 && y0.x <= sy1) ? 1u : 0u;
        m4 |= (j0 + 1 < pcnt && y1.y >= sy0 && y1.x <= sy1) ? 2u : 0u;
        m4 |= (j0 + 2 < pcnt && y2.y >= sy0 && y2.x <= sy1) ? 4u : 0u;
        m4 |= (j0 + 3 < pcnt && y3.y >= sy0 && y3.x <= sy1) ? 8u : 0u;
        int cnt = __popc(m4);
        int incl = wscan_incl(cnt, lane);
        if (lane == 31) swc[warp] = incl;
        __syncthreads();
        if (warp == 0) {
            int v = swc[lane];
            int iv = wscan_incl(v, lane);
            swe[lane] = iv - v;
        }
        __syncthreads();
        int basep = swe[warp] + incl - cnt;
        int gis[4] = {gi0, gi1, gi2, gi3};
        #pragma unroll
        for (int k = 0; k < 4; ++k)
            if (m4 & (1u << k)) {
                int p = basep + __popc(m4 & ((1u << k) - 1u));
                if (p < SCAP) slist[p] = gis[k];
            }
        __syncthreads();
        listCnt = min(swe[31] + swc[31], SCAP);
    }

    // ===== Phase D: render 64 px x 16 depth segments =====
    {
        int seg = tid >> 6;                // 0..15 front-to-back segments
        int l   = tid & 63;                // pixel within 32x2 slab
        int col = l & 31;
        int row = l >> 5;                  // uniform per warp
        float slabY = sy0;                 // row-0 y coordinate
        int px = (tile & 3) * TILE + col;
        int py = (int)sy0 + row;
        float fx = (float)px;

        int cnt = listCnt;
        int q   = (cnt + NSEG - 1) >> 4;
        int sbeg = seg * q;
        int send = min(cnt, sbeg + q);

        float T = 1.0f;
        float cr = 0.0f, cg = 0.0f, cbl = 0.0f, cd = 0.0f;

        for (int base = 0; base < q; base += BATCH) {
            int mload = send - (sbeg + base);
            // loader: precompute per-(splat,row) coefficients
            if (l < mload) {
                int gi = slist[sbeg + base + l];
                float4 p1 = g_s1[gi];      // mx, A', B', C'
                float2 t2 = g_sT[gi];      // my, ol2
                float4 p3 = g_s3[gi];
                float dy0 = slabY - t2.x;
                float dy1 = dy0 + 1.0f;
                float c1a = p1.z * dy0;
                float c0a = fmaf(p1.w * dy0, dy0, t2.y);
                float c1b = p1.z * dy1;
                float c0b = fmaf(p1.w * dy1, dy1, t2.y);
                sbR[(0 * 16 + seg) * BATCH + l] = make_float4(p1.x, p1.y, c1a, c0a);
                sbR[(1 * 16 + seg) * BATCH + l] = make_float4(p1.x, p1.y, c1b, c0b);
                sb3[seg * BATCH + l] = p3;
            }
            __syncthreads();

            int m = min(BATCH, mload);
            if (m > 0 && T >= TERM_T) {
                const float4* rb = &sbR[(row * 16 + seg) * BATCH];
                const float4* cb = &sb3[seg * BATCH];
                #pragma unroll 4
                for (int k = 0; k < m; ++k) {
                    float4 pr = rb[k];                 // mx, A', c1, c0
                    float dx = fx - pr.x;
                    float pw = fmaf(fmaf(pr.y, dx, pr.z), dx, pr.w);
                    float alpha = fminf(ex2f(pw), 0.99f);
                    float wgt = T * alpha;
                    float4 p3 = cb[k];
                    cr  = fmaf(wgt, p3.x, cr);
                    cg  = fmaf(wgt, p3.y, cg);
                    cbl = fmaf(wgt, p3.z, cbl);
                    cd  = fmaf(wgt, p3.w, cd);
                    T  -= wgt;
                }
            }
            if (__syncthreads_and(T < TERM_T)) break;
        }

        // fold 16 depth segments front-to-back: c = cF + TF*cB, T = TF*TB
        __syncthreads();                   // batches dead; alias fold buffer
        pres[0 * BLOCK + tid] = cr;  pres[1 * BLOCK + tid] = cg;
        pres[2 * BLOCK + tid] = cbl; pres[3 * BLOCK + tid] = cd;
        pres[4 * BLOCK + tid] = T;
        __syncthreads();
        if (tid < 64) {
            float crO = pres[0 * BLOCK + tid + 15 * 64];
            float cgO = pres[1 * BLOCK + tid + 15 * 64];
            float cbO = pres[2 * BLOCK + tid + 15 * 64];
            float cdO = pres[3 * BLOCK + tid + 15 * 64];
            float TO  = pres[4 * BLOCK + tid + 15 * 64];
            #pragma unroll
            for (int s = 14; s >= 0; --s) {
                int o = tid + s * 64;
                float Tf = pres[4 * BLOCK + o];
                crO = fmaf(Tf, crO, pres[0 * BLOCK + o]);
                cgO = fmaf(Tf, cgO, pres[1 * BLOCK + o]);
                cbO = fmaf(Tf, cbO, pres[2 * BLOCK + o]);
                cdO = fmaf(Tf, cdO, pres[3 * BLOCK + o]);
                TO *= Tf;
            }
            int pix = py * W + px;
            out[pix * 3 + 0]     = crO + TO;
            out[pix * 3 + 1]     = cgO + TO;
            out[pix * 3 + 2]     = cbO + TO;
            out[H * W * 3 + pix] = cdO;
            out[H * W * 4 + pix] = 1.0f - TO;
        }
    }
}

// ---------------- launch ----------------
extern "C" void kernel_launch(void* const* d_in, const int* in_sizes, int n_in,
                              void* d_out, int out_size)
{
    const float* means   = (const float*)d_in[0];
    const float* cov     = (const float*)d_in[1];
    const float* color   = (const float*)d_in[2];
    const float* opacity = (const float*)d_in[3];
    const float* depths  = (const float*)d_in[4];
    int n = in_sizes[4];
    if (n > MAXN) n = MAXN;

    static int configured = 0;
    if (!configured) {
        cudaFuncSetAttribute(mega_kernel,
                             cudaFuncAttributeMaxDynamicSharedMemorySize, SMEM_BYTES);
        configured = 1;
    }
    mega_kernel<<<GRID, BLOCK, SMEM_BYTES>>>(means, cov, color, opacity, depths, n,
                                             (float*)d_out);
}